// round 14
// baseline (speedup 1.0000x reference)
#include <cuda_runtime.h>
#include <math.h>
#include <stdint.h>

#define Bsz 128
#define Ssz 1024
#define Hsz 768
#define MAXV 25
#define NTOK 50                 // 2*MAXV
#define S_LEVI (Ssz - NTOK)     // 974
#define H4 (Hsz / 4)            // 192 float4 per row

// ---- GEMM config (R14: 4b x 8h microtile, 64b x 128h x 24k blocks) ----
#define KSPLIT 32               // 768 / 32 = 24 k per block
#define KS   24                 // k per block
#define GTB  64                 // batches per block
#define GTH  128                // h-outputs per block
#define SPST 65                 // sP row stride (floats)
#define SWST 132                // sW row stride (floats), 16B multiple

// Scratch (allocation-free rule: device globals)
__device__ float g_pooled[Bsz * Hsz];
__device__ float g_part[KSPLIT * Bsz * Hsz];   // 12.6 MB partial sums

__device__ __forceinline__ float warp_sum(float v) {
#pragma unroll
    for (int o = 16; o > 0; o >>= 1) v += __shfl_xor_sync(0xffffffffu, v, o);
    return v;
}

__device__ __forceinline__ uint32_t smem_u32(const void* p) {
    uint32_t a;
    asm("{ .reg .u64 t; cvta.to.shared.u64 t, %1; cvt.u32.u64 %0, t; }"
        : "=r"(a) : "l"(p));
    return a;
}

// pack (f,f) into a 64-bit f32x2 register
#define PACK_DUP(dst, f) \
    asm("mov.b64 %0, {%1, %1};" : "=l"(dst) : "r"(__float_as_uint(f)))

// d.lo += a.lo*b.lo; d.hi += a.hi*b.hi  (two fp32 FMAs, one FFMA2)
#define FMA2(d, a, b) \
    asm("fma.rn.f32x2 %0, %1, %2, %0;" : "+l"(d) : "l"(a), "l"(b))

// Detect verb_count dtype (int64 vs int32) and return v for batch b.
// 64 odd-word samples all zero <=> int64 (values < 25). Warp-collective.
__device__ __forceinline__ int load_verb(const int* __restrict__ verb32,
                                         int b, int lane) {
    int a = verb32[2 * lane + 1];
    int c = verb32[2 * lane + 65];
    unsigned nz = __ballot_sync(0xffffffffu, (a | c) != 0);
    return nz ? verb32[b] : verb32[2 * b];
}

// ---------------------------------------------------------------------------
// Kernel 1: fused masked-attention pooling. One block per batch, 768 threads.
// Active ordinals j in [0,2v): token t = j<v ? j : j-v+MAXV. Inactive rows
// have weight exactly 0 in the reference and are never touched. The
// subject-hidden score term is a per-batch constant over active tokens and
// cancels exactly in softmax; skipped.
// ---------------------------------------------------------------------------
__global__ __launch_bounds__(768, 1)
void pool_kernel(const float* __restrict__ hidden,
                 const int*   __restrict__ verb32,
                 const float* __restrict__ align_w,   // [2H]
                 float*       __restrict__ pooled)    // [B,H]
{
    __shared__ float  s_scores[NTOK];     // by active ordinal j
    __shared__ float  s_wact[NTOK];       // weight of ordinal j
    __shared__ float4 s_part[4][H4];      // 12 KB cross-group pooling partials

    const int b    = blockIdx.x;
    const int tid  = threadIdx.x;
    const int warp = tid >> 5;
    const int lane = tid & 31;

    const int v    = load_verb(verb32, b, lane);   // warp-uniform
    const int nact = 2 * v;

    if (tid < NTOK) s_scores[tid] = -INFINITY;
    __syncthreads();

    const float* __restrict__ bbase = hidden + ((size_t)b * Ssz + S_LEVI) * Hsz;
    const float4* __restrict__ base4 = (const float4*)bbase;
    const float4* __restrict__ w4    = (const float4*)(align_w + Hsz);

    // --- pass 1: scores, warp per active ordinal (24 warps, <=2 rounds) ---
    for (int j = warp; j < nact; j += 24) {
        const int t = (j < v) ? j : (j - v + MAXV);
        const float4* row4 = base4 + (size_t)t * H4;
        float4 a = make_float4(0.f, 0.f, 0.f, 0.f);
#pragma unroll
        for (int i = 0; i < 6; i++) {
            float4 hv = row4[lane + i * 32];
            float4 wv = w4[lane + i * 32];
            a.x = fmaf(hv.x, wv.x, a.x);
            a.y = fmaf(hv.y, wv.y, a.y);
            a.z = fmaf(hv.z, wv.z, a.z);
            a.w = fmaf(hv.w, wv.w, a.w);
        }
        float s = warp_sum((a.x + a.y) + (a.z + a.w));
        if (lane == 0) s_scores[j] = s;
    }
    __syncthreads();

    // --- pass 2: softmax over ordinals (warp 0) ---
    if (warp == 0) {
        float a  = (lane < NTOK)      ? s_scores[lane]      : -INFINITY;
        float b2 = (lane + 32 < NTOK) ? s_scores[lane + 32] : -INFINITY;
        float m = fmaxf(a, b2);
#pragma unroll
        for (int o = 16; o > 0; o >>= 1)
            m = fmaxf(m, __shfl_xor_sync(0xffffffffu, m, o));
        if (!isfinite(m)) m = 0.f;
        float e1 = (a  > -INFINITY) ? expf(a  - m) : 0.f;
        float e2 = (b2 > -INFINITY) ? expf(b2 - m) : 0.f;
        float denom = warp_sum(e1 + e2);
        float inv = (denom > 0.f) ? (1.f / fmaxf(denom, 1e-30f)) : 0.f;
        if (lane < NTOK)      s_wact[lane]      = e1 * inv;
        if (lane + 32 < NTOK) s_wact[lane + 32] = e2 * inv;
    }
    __syncthreads();

    // --- pass 3: pooled, (4 token-groups x 192 h-chunks) then smem reduce ---
    {
        const int grp = tid / H4;     // 0..3
        const int h4  = tid % H4;     // 0..191
        float4 acc = make_float4(0.f, 0.f, 0.f, 0.f);
#pragma unroll 2
        for (int j = grp; j < nact; j += 4) {
            const int t = (j < v) ? j : (j - v + MAXV);
            const float w = s_wact[j];
            float4 hv = base4[(size_t)t * H4 + h4];
            acc.x = fmaf(w, hv.x, acc.x);
            acc.y = fmaf(w, hv.y, acc.y);
            acc.z = fmaf(w, hv.z, acc.z);
            acc.w = fmaf(w, hv.w, acc.w);
        }
        s_part[grp][h4] = acc;
    }
    __syncthreads();

    if (tid < H4) {
        float4 p0 = s_part[0][tid], p1 = s_part[1][tid];
        float4 p2 = s_part[2][tid], p3 = s_part[3][tid];
        float4 r;
        r.x = (p0.x + p1.x) + (p2.x + p3.x);
        r.y = (p0.y + p1.y) + (p2.y + p3.y);
        r.z = (p0.z + p1.z) + (p2.z + p3.z);
        r.w = (p0.w + p1.w) + (p2.w + p3.w);
        ((float4*)pooled)[(size_t)b * H4 + tid] = r;
    }
}

// ---------------------------------------------------------------------------
// Kernel 2: split-K partial GEMM. One 64b x 128h x 24k tile per block,
// grid (6,2,32)=384 blocks, 256 threads. Per-thread 4b x 8h microtile via
// FFMA2; W pairs come packed straight from ld.shared.v2.u64 (no pack),
// only the 4 P broadcasts are packed. 32 independent acc chains = high ILP.
// No atomics; partials reduced by a separate epilogue (deterministic).
// ---------------------------------------------------------------------------
__global__ __launch_bounds__(256, 4)
void gemm_partial(const float* __restrict__ P,     // [B,H] pooled
                  const float* __restrict__ W,     // [H,H] out_w (k contiguous)
                  float*       __restrict__ part)  // [KSPLIT,B,H]
{
    __shared__ __align__(16) float sP[KS][SPST];   // k-major: 6.2 KB
    __shared__ __align__(16) float sW[KS][SWST];   // k-major: 12.7 KB

    const int tid  = threadIdx.x;
    const int h0   = blockIdx.x * GTH;
    const int b0   = blockIdx.y * GTB;
    const int ks0  = blockIdx.z * KS;

    // --- load P tile 64 x 24 (6 float4 per row), transpose to k-major ---
#pragma unroll
    for (int i = 0; i < 2; i++) {
        int idx = tid + i * 256;            // 0..383
        if (idx < GTB * 6) {
            int row = idx / 6, c4 = idx % 6;
            float4 vv = *(const float4*)&P[(size_t)(b0 + row) * Hsz + ks0 + c4 * 4];
            sP[c4 * 4 + 0][row] = vv.x;
            sP[c4 * 4 + 1][row] = vv.y;
            sP[c4 * 4 + 2][row] = vv.z;
            sP[c4 * 4 + 3][row] = vv.w;
        }
    }
    // --- load W tile 128 x 24 (6 float4 per row), transpose to k-major ---
#pragma unroll
    for (int i = 0; i < 3; i++) {
        int idx = tid + i * 256;            // 0..767
        int hh = idx / 6, c4 = idx % 6;
        float4 vv = *(const float4*)&W[(size_t)(h0 + hh) * Hsz + ks0 + c4 * 4];
        sW[c4 * 4 + 0][hh] = vv.x;
        sW[c4 * 4 + 1][hh] = vv.y;
        sW[c4 * 4 + 2][hh] = vv.z;
        sW[c4 * 4 + 3][hh] = vv.w;
    }
    __syncthreads();

    // --- compute: b rows {rb, rb+16, rb+32, rb+48}, h cols c*8 .. c*8+7 ---
    const int warp = tid >> 5;
    const int lane = tid & 31;
    const int c    = lane & 15;                    // 0..15 -> 8 h each
    const int rb   = (warp << 1) | (lane >> 4);    // 0..15

    const uint32_t swa = smem_u32(&sW[0][c * 8]);

    unsigned long long acc[16];   // [b i][h-pair j]
#pragma unroll
    for (int i = 0; i < 16; i++) acc[i] = 0ull;

#pragma unroll
    for (int k = 0; k < KS; k++) {
        unsigned long long w01, w23, w45, w67;
        asm("ld.shared.v2.u64 {%0, %1}, [%2];"
            : "=l"(w01), "=l"(w23) : "r"(swa + k * (SWST * 4)));
        asm("ld.shared.v2.u64 {%0, %1}, [%2];"
            : "=l"(w45), "=l"(w67) : "r"(swa + k * (SWST * 4) + 16));
        float p0 = sP[k][rb];
        float p1 = sP[k][rb + 16];
        float p2 = sP[k][rb + 32];
        float p3 = sP[k][rb + 48];
        unsigned long long pp0, pp1, pp2, pp3;
        PACK_DUP(pp0, p0); PACK_DUP(pp1, p1);
        PACK_DUP(pp2, p2); PACK_DUP(pp3, p3);
        FMA2(acc[0],  pp0, w01); FMA2(acc[1],  pp0, w23);
        FMA2(acc[2],  pp0, w45); FMA2(acc[3],  pp0, w67);
        FMA2(acc[4],  pp1, w01); FMA2(acc[5],  pp1, w23);
        FMA2(acc[6],  pp1, w45); FMA2(acc[7],  pp1, w67);
        FMA2(acc[8],  pp2, w01); FMA2(acc[9],  pp2, w23);
        FMA2(acc[10], pp2, w45); FMA2(acc[11], pp2, w67);
        FMA2(acc[12], pp3, w01); FMA2(acc[13], pp3, w23);
        FMA2(acc[14], pp3, w45); FMA2(acc[15], pp3, w67);
    }

    // --- store partials: 4 rows x 2 float4 per thread ---
    float* base = part + ((size_t)blockIdx.z * Bsz) * Hsz;
#pragma unroll
    for (int i = 0; i < 4; i++) {
        float* dst = &base[(size_t)(b0 + rb + 16 * i) * Hsz + h0 + c * 8];
        float4 s;
        asm("mov.b64 {%0, %1}, %2;" : "=f"(s.x), "=f"(s.y) : "l"(acc[i * 4 + 0]));
        asm("mov.b64 {%0, %1}, %2;" : "=f"(s.z), "=f"(s.w) : "l"(acc[i * 4 + 1]));
        *(float4*)dst = s;
        asm("mov.b64 {%0, %1}, %2;" : "=f"(s.x), "=f"(s.y) : "l"(acc[i * 4 + 2]));
        asm("mov.b64 {%0, %1}, %2;" : "=f"(s.z), "=f"(s.w) : "l"(acc[i * 4 + 3]));
        *(float4*)(dst + 4) = s;
    }
}

// ---------------------------------------------------------------------------
// Kernel 3: epilogue. out[b,h] = tanh( sum_z part[z][b][h] + bias[h] )
// 192 blocks x 128 threads; 32 INDEPENDENT z-loads per thread (MLP=32).
// Fixed z order -> deterministic.
// ---------------------------------------------------------------------------
__global__ __launch_bounds__(128)
void epilogue(const float* __restrict__ part,
              const float* __restrict__ bias,
              float*       __restrict__ out)
{
    const int idx = blockIdx.x * 128 + threadIdx.x;   // 0..24575 float4 slots
    const float4* p4 = (const float4*)part + idx;
    const int h4 = idx % H4;

    float4 s = make_float4(0.f, 0.f, 0.f, 0.f);
#pragma unroll
    for (int z = 0; z < KSPLIT; z++) {
        float4 v = p4[(size_t)z * (Bsz * H4)];
        s.x += v.x; s.y += v.y; s.z += v.z; s.w += v.w;
    }
    float4 bi = ((const float4*)bias)[h4];
    float4 o;
    o.x = tanhf(s.x + bi.x);
    o.y = tanhf(s.y + bi.y);
    o.z = tanhf(s.z + bi.z);
    o.w = tanhf(s.w + bi.w);
    ((float4*)out)[idx] = o;
}

// ---------------------------------------------------------------------------
extern "C" void kernel_launch(void* const* d_in, const int* in_sizes, int n_in,
                              void* d_out, int out_size)
{
    const float* hidden   = (const float*)d_in[0];
    const int*   verb32   = (const int*)  d_in[1];  // int32 view; dtype auto-detected
    const float* align_w  = (const float*)d_in[3];
    const float* out_w    = (const float*)d_in[5];
    const float* out_b    = (const float*)d_in[6];
    float* out = (float*)d_out;

    float* pooled = nullptr;
    float* part   = nullptr;
    cudaGetSymbolAddress((void**)&pooled, g_pooled);
    cudaGetSymbolAddress((void**)&part,   g_part);

    pool_kernel<<<Bsz, 768>>>(hidden, verb32, align_w, pooled);
    gemm_partial<<<dim3(Hsz / GTH, Bsz / GTB, KSPLIT), 256>>>(pooled, out_w, part);
    epilogue<<<(Bsz * H4) / 128, 128>>>(part, out_b, out);
}